// round 4
// baseline (speedup 1.0000x reference)
#include <cuda_runtime.h>
#include <cuda_fp16.h>
#include <cstdint>

// LSTMPredictor: persistent-CTA fused 2-layer LSTM.
// B=8192, T=2048 (+64 autoregressive), H=51. Output (8192, 2112) fp32.
//
// Per CTA: 64 batch rows for all 2112 steps. Gate GEMVs via fp16 mma.m16n8k16
// (fp32 accum): G[64 x 208] = A[64 x 64] @ W[64 x 208].
//   K layout: 0..50 = h, 51 = x (or fed-back out), 52 = 1.0 (bias row), 53..63 = 0
//   N layout: permuted gate rows n = 4j+q, q in {i,f,g,o} -> float4/unit reads
// Weights pre-baked to mma B-fragment order by a tiny prep kernel (global
// scratch d_Wf), copied to SMEM once per launch.

#define NLAY_OFF 6656          // uint32 per layer in fragment cache
#define WF_TOTAL 13312
#define GSTR 216               // G row stride (floats)  - bank-conflict-free
#define ASTR 72                // A row stride (halves)  - bank-conflict-free
#define BT   64
#define TPB  256
#define TSEQ 2048
#define TTOT 2112

__device__ __align__(16) uint32_t d_Wf[WF_TOTAL];

__device__ __forceinline__ float sig_acc(float x) {
    return __fdividef(1.0f, 1.0f + __expf(-x));
}
__device__ __forceinline__ float tanh_acc(float x) {
    float ax = fabsf(x);
    float e  = __expf(-2.0f * ax);
    float r  = __fdividef(1.0f - e, 1.0f + e);
    return copysignf(r, x);
}
__device__ __forceinline__ float tanh_ap(float x) {
    float y; asm("tanh.approx.f32 %0, %1;" : "=f"(y) : "f"(x)); return y;
}
__device__ __forceinline__ float sig_ap(float x) {
    return 0.5f + 0.5f * tanh_ap(0.5f * x);
}

// ---------------------------------------------------------------------------
// Build fragment-ordered fp16 weights.
// u = L*6656 + ((kt*26 + nt)*32 + lane)*2 + r   (r: 0 -> b0 frag, 1 -> b1)
// value pair = W[k0][n], W[k0+1][n], k0 = kt*16 + r*8 + 2*tig, n = nt*8 + g
// n -> original gate row: j = n>>2, q = n&3, row = q*51 + j  (q = i,f,g,o)
__global__ void prep_weights(const float* __restrict__ Wih1, const float* __restrict__ Whh1,
                             const float* __restrict__ bih1, const float* __restrict__ bhh1,
                             const float* __restrict__ Wih2, const float* __restrict__ Whh2,
                             const float* __restrict__ bih2, const float* __restrict__ bhh2) {
    int u = blockIdx.x * blockDim.x + threadIdx.x;
    if (u >= WF_TOTAL) return;
    int L    = u / NLAY_OFF;
    int w    = u - L * NLAY_OFF;
    int r    = w & 1;
    int lane = (w >> 1) & 31;
    int t2   = w >> 6;
    int nt   = t2 % 26;
    int kt   = t2 / 26;
    int n    = nt * 8 + (lane >> 2);
    int k0   = kt * 16 + r * 8 + 2 * (lane & 3);
    float v[2];
#pragma unroll
    for (int i = 0; i < 2; i++) {
        int k = k0 + i;
        float val = 0.0f;
        if (n < 204) {
            int j = n >> 2, q = n & 3;
            int row = q * 51 + j;
            if (k < 51)
                val = (L == 0) ? Whh1[row * 51 + k]
                               : (Wih2[row * 51 + k] + Whh2[row * 51 + k]);
            else if (k == 51)
                val = (L == 0) ? Wih1[row] : 0.0f;
            else if (k == 52)
                val = (L == 0) ? (bih1[row] + bhh1[row]) : (bih2[row] + bhh2[row]);
        }
        v[i] = val;
    }
    __half2 h = __floats2half2_rn(v[0], v[1]);
    d_Wf[u] = *(uint32_t*)&h;
}

// ---------------------------------------------------------------------------
__global__ void __launch_bounds__(TPB, 1)
lstm_main(const float* __restrict__ x,
          const float* __restrict__ Wout, const float* __restrict__ bout,
          float* __restrict__ out) {
    extern __shared__ char smem_raw[];
    uint32_t* Ws = (uint32_t*)smem_raw;              // 53248 B  weight frags
    float*    Gs = (float*)(smem_raw + 53248);       // 55296 B  gates 64x216
    __half*   As = (__half*)(smem_raw + 108544);     //  9216 B  A 64x72 (fp16)
    float*    Cs = (float*)(smem_raw + 117760);      // 13056 B  c-state flat
    float*    Rs = (float*)(smem_raw + 130816);      // 13056 B  h2*Wout partials
    float*    wo = (float*)(smem_raw + 143872);      //   208 B  Wout + bout

    const int tid  = threadIdx.x;
    const int lane = tid & 31;
    const int wrp  = tid >> 5;
    const int gb0  = blockIdx.x * BT;

    // ---- one-time init ----
    {
        const uint4* src = (const uint4*)d_Wf;
        uint4* dst = (uint4*)Ws;
        for (int i = tid; i < 3328; i += TPB) dst[i] = src[i];
        for (int i = tid; i < 3264; i += TPB) Cs[i] = 0.0f;
        for (int i = tid; i < BT * ASTR; i += TPB) {
            int col = i % ASTR;
            As[i] = __float2half_rn(col == 52 ? 1.0f : 0.0f);
        }
        if (tid < 51) wo[tid] = Wout[tid];
        if (tid == 51) wo[51] = bout[0];
    }

    const int g   = lane >> 2, tig = lane & 3;
    const int mg  = wrp >> 2;                    // m-group: 2 M-tiles each
    const int nq  = wrp & 3;                     // n-quarter of 26 n-tiles
    const int ntBeg = (nq < 2) ? nq * 7 : 14 + (nq - 2) * 6;
    const int ntCnt = (nq < 2) ? 7 : 6;

    float xcur = 0.0f, xnext = 0.0f;
    if (tid < 64) xcur = x[(size_t)(gb0 + tid) * TSEQ];

    __syncthreads();

#pragma unroll 1
    for (int t = 0; t < TTOT; t++) {
        // stage x (future phase keeps fed-back out in slot 51); prefetch next x
        if (t < TSEQ && tid < 64)
            As[tid * ASTR + 51] = __float2half_rn(xcur);
        if (tid < 64 && t + 1 < TSEQ)
            xnext = x[(size_t)(gb0 + tid) * TSEQ + (t + 1)];
        __syncthreads();

#pragma unroll 1
        for (int L = 0; L < 2; L++) {
            // ---- GEMM: G = A @ W_L ----
            const uint32_t* WL = Ws + L * NLAY_OFF;
            uint32_t a[2][4][4];
#pragma unroll
            for (int mt = 0; mt < 2; mt++) {
                int r0 = (mg * 2 + mt) * 16 + g;
#pragma unroll
                for (int kt = 0; kt < 4; kt++) {
                    int c0 = kt * 16 + 2 * tig;
                    a[mt][kt][0] = *(const uint32_t*)&As[r0 * ASTR + c0];
                    a[mt][kt][1] = *(const uint32_t*)&As[(r0 + 8) * ASTR + c0];
                    a[mt][kt][2] = *(const uint32_t*)&As[r0 * ASTR + c0 + 8];
                    a[mt][kt][3] = *(const uint32_t*)&As[(r0 + 8) * ASTR + c0 + 8];
                }
            }
#pragma unroll 1
            for (int nti = 0; nti < ntCnt; nti++) {
                int nt = ntBeg + nti;
                uint32_t b[4][2];
#pragma unroll
                for (int kt = 0; kt < 4; kt++) {
                    uint2 bb = *(const uint2*)&WL[(((kt * 26) + nt) * 32 + lane) * 2];
                    b[kt][0] = bb.x; b[kt][1] = bb.y;
                }
#pragma unroll
                for (int mt = 0; mt < 2; mt++) {
                    float d0 = 0.f, d1 = 0.f, d2 = 0.f, d3 = 0.f;
#pragma unroll
                    for (int kt = 0; kt < 4; kt++) {
                        asm volatile(
                            "mma.sync.aligned.m16n8k16.row.col.f32.f16.f16.f32 "
                            "{%0,%1,%2,%3},{%4,%5,%6,%7},{%8,%9},{%0,%1,%2,%3};\n"
                            : "+f"(d0), "+f"(d1), "+f"(d2), "+f"(d3)
                            : "r"(a[mt][kt][0]), "r"(a[mt][kt][1]),
                              "r"(a[mt][kt][2]), "r"(a[mt][kt][3]),
                              "r"(b[kt][0]), "r"(b[kt][1]));
                    }
                    int r0 = (mg * 2 + mt) * 16 + g;
                    int cc = nt * 8 + 2 * tig;
                    *(float2*)&Gs[r0 * GSTR + cc]       = make_float2(d0, d1);
                    *(float2*)&Gs[(r0 + 8) * GSTR + cc] = make_float2(d2, d3);
                }
            }
            __syncthreads();

            // ---- activations ----
            if (L == 0) {
#pragma unroll 1
                for (int i = 0; i < 13; i++) {
                    int idx = tid + i * TPB;
                    if (idx < 3264) {
                        int bb = idx / 51;
                        int j  = idx - bb * 51;
                        float4 gv = *(const float4*)&Gs[bb * GSTR + 4 * j];
                        float ig = sig_acc(gv.x);
                        float fg = sig_acc(gv.y);
                        float gg = tanh_acc(gv.z);
                        float og = sig_acc(gv.w);
                        float c  = fg * Cs[idx] + ig * gg;
                        Cs[idx]  = c;
                        As[bb * ASTR + j] = __float2half_rn(og * tanh_acc(c));
                    }
                }
            } else {
#pragma unroll 1
                for (int i = 0; i < 13; i++) {
                    int idx = tid + i * TPB;
                    if (idx < 3264) {
                        int bb = idx / 51;
                        int j  = idx - bb * 51;
                        float4 gv = *(const float4*)&Gs[bb * GSTR + 4 * j];
                        float ig = sig_ap(gv.x);
                        float fg = sig_ap(gv.y);
                        float gg = tanh_ap(gv.z);
                        float og = sig_ap(gv.w);
                        float c2 = fg * Cs[idx] + ig * gg;   // c not updated (layer2)
                        Rs[idx]  = og * tanh_ap(c2) * wo[j];
                    }
                }
            }
            __syncthreads();
        }

        // ---- emit: out[b] = sum_j Rs[b][j] + bout; feed back into x slot ----
        {
            int bb = tid >> 2, q = tid & 3;
            int jb = q * 13;
            int je = (q == 3) ? 51 : jb + 13;
            float s = 0.0f;
            for (int j = jb; j < je; j++) s += Rs[bb * 51 + j];
            s += __shfl_xor_sync(0xffffffffu, s, 1);
            s += __shfl_xor_sync(0xffffffffu, s, 2);
            if (q == 0) {
                float o = s + wo[51];
                out[(size_t)(gb0 + bb) * TTOT + t] = o;
                As[bb * ASTR + 51] = __float2half_rn(o);
            }
        }
        xcur = xnext;
        __syncthreads();
    }
}

// ---------------------------------------------------------------------------
extern "C" void kernel_launch(void* const* d_in, const int* in_sizes, int n_in,
                              void* d_out, int out_size) {
    const float* x    = (const float*)d_in[0];
    const float* Wih1 = (const float*)d_in[1];
    const float* Whh1 = (const float*)d_in[2];
    const float* bih1 = (const float*)d_in[3];
    const float* bhh1 = (const float*)d_in[4];
    const float* Wih2 = (const float*)d_in[5];
    const float* Whh2 = (const float*)d_in[6];
    const float* bih2 = (const float*)d_in[7];
    const float* bhh2 = (const float*)d_in[8];
    const float* Wout = (const float*)d_in[9];
    const float* bouT = (const float*)d_in[10];
    float* out = (float*)d_out;

    cudaFuncSetAttribute(lstm_main, cudaFuncAttributeMaxDynamicSharedMemorySize, 150 * 1024);

    prep_weights<<<52, 256>>>(Wih1, Whh1, bih1, bhh1, Wih2, Whh2, bih2, bhh2);
    lstm_main<<<128, TPB, 144128>>>(x, Wout, bouT, out);
}

// round 5
// speedup vs baseline: 1.9591x; 1.9591x over previous
#include <cuda_runtime.h>
#include <cuda_fp16.h>
#include <cstdint>

// LSTMPredictor: persistent-CTA fused 2-layer LSTM, in-register activations.
// B=8192, T=2048 (+64 autoregressive), H=51. Output (8192, 2112) fp32.
//
// Grid 256 CTAs x 256 thr, BT=32 batch rows each, 2 CTAs/SM co-resident.
// Gate GEMV via fp16 mma.m16n8k16 (fp32 accum): G[32 x 208] = A[32 x 64] @ W.
//   K: 0..50 = h, 51 = x (or fed-back out), 52 = 1.0 (bias row), 53..63 = 0
//   N: permuted gate rows n = 4j+q, q in {i,f,g,o}. D-fragment layout puts
//      (i,f) on even-tig lanes and (g,o) on odd-tig lanes of the same j ->
//      one shfl_xor(1) gives each lane all 4 gates of one (row, j); the whole
//      activation runs in registers (no gate matrix in SMEM at all).
// Weights pre-baked to mma B-fragment order (global scratch d_Wf), copied to
// SMEM once per CTA.

#define NLAY_OFF 6656          // uint32 per layer in fragment cache
#define WF_TOTAL 13312
#define ASTR 72                // A row stride (halves)
#define CSTR 51
#define RSTR 51
#define BT   32
#define TPB  256
#define TSEQ 2048
#define TTOT 2112
#define NCTA 256

__device__ __align__(16) uint32_t d_Wf[WF_TOTAL];

__device__ __forceinline__ float tanh_ap(float x) {
    float y; asm("tanh.approx.f32 %0, %1;" : "=f"(y) : "f"(x)); return y;
}
__device__ __forceinline__ float sig_ap(float x) {
    return fmaf(tanh_ap(0.5f * x), 0.5f, 0.5f);
}

// ---------------------------------------------------------------------------
// Build fragment-ordered fp16 weights (same encoding as the R4 kernel, which
// passed: verified correct).
// u = L*6656 + ((kt*26 + nt)*32 + lane)*2 + r   (r: 0 -> b0 frag, 1 -> b1)
// pair = W[k0][n], W[k0+1][n], k0 = kt*16 + r*8 + 2*(lane&3), n = nt*8 + (lane>>2)
// n -> gate row: j = n>>2, q = n&3, row = q*51 + j  (q = i,f,g,o)
__global__ void prep_weights(const float* __restrict__ Wih1, const float* __restrict__ Whh1,
                             const float* __restrict__ bih1, const float* __restrict__ bhh1,
                             const float* __restrict__ Wih2, const float* __restrict__ Whh2,
                             const float* __restrict__ bih2, const float* __restrict__ bhh2) {
    int u = blockIdx.x * blockDim.x + threadIdx.x;
    if (u >= WF_TOTAL) return;
    int L    = u / NLAY_OFF;
    int w    = u - L * NLAY_OFF;
    int r    = w & 1;
    int lane = (w >> 1) & 31;
    int t2   = w >> 6;
    int nt   = t2 % 26;
    int kt   = t2 / 26;
    int n    = nt * 8 + (lane >> 2);
    int k0   = kt * 16 + r * 8 + 2 * (lane & 3);
    float v[2];
#pragma unroll
    for (int i = 0; i < 2; i++) {
        int k = k0 + i;
        float val = 0.0f;
        if (n < 204) {
            int j = n >> 2, q = n & 3;
            int row = q * 51 + j;
            if (k < 51)
                val = (L == 0) ? Whh1[row * 51 + k]
                               : (Wih2[row * 51 + k] + Whh2[row * 51 + k]);
            else if (k == 51)
                val = (L == 0) ? Wih1[row] : 0.0f;
            else if (k == 52)
                val = (L == 0) ? (bih1[row] + bhh1[row]) : (bih2[row] + bhh2[row]);
        }
        v[i] = val;
    }
    __half2 h = __floats2half2_rn(v[0], v[1]);
    d_Wf[u] = *(uint32_t*)&h;
}

// ---------------------------------------------------------------------------
__global__ void __launch_bounds__(TPB, 2)
lstm_main(const float* __restrict__ x,
          const float* __restrict__ Wout, const float* __restrict__ bout,
          float* __restrict__ out) {
    extern __shared__ char smem_raw[];
    uint32_t* Ws = (uint32_t*)smem_raw;               // 53248 B  weight frags
    __half*   As = (__half*)(smem_raw + 53248);       //  4608 B  A 32x72 fp16
    float*    Cs = (float*)(smem_raw + 57856);        //  6528 B  c-state 32x51
    float*    Rs = (float*)(smem_raw + 64384);        //  6528 B  h2*Wout partials

    const int tid  = threadIdx.x;
    const int lane = tid & 31;
    const int wrp  = tid >> 5;
    const int gb0  = blockIdx.x * BT;
    const int g    = lane >> 2, tig = lane & 3;
    const int oddl = tig & 1;
    const int mg   = wrp >> 2;            // 0..1: 16-row m-tile
    const int nq   = wrp & 3;             // n-quarter: 7 n-tiles each (2 dummy)
    const int ntBeg = nq * 7;

    // ---- one-time init ----
    {
        const uint4* src = (const uint4*)d_Wf;
        uint4* dst = (uint4*)Ws;
        for (int i = tid; i < 3328; i += TPB) dst[i] = src[i];
        for (int i = tid; i < BT * CSTR; i += TPB) Cs[i] = 0.0f;
        for (int i = tid; i < BT * ASTR; i += TPB)
            As[i] = __float2half_rn((i % ASTR) == 52 ? 1.0f : 0.0f);
    }
    const float bo = bout[0];
    float woj[7];
#pragma unroll
    for (int ni = 0; ni < 7; ni++) {
        int j = 2 * (ntBeg + ni) + (tig >> 1);
        woj[ni] = (j < 51) ? Wout[j] : 0.0f;
    }
    const int myrow = mg * 16 + g + (oddl ? 8 : 0);

    float xcur = 0.0f, xnext = 0.0f;
    if (tid < BT) xcur = x[(size_t)(gb0 + tid) * TSEQ];
    __syncthreads();

#pragma unroll 1
    for (int t = 0; t < TTOT; t++) {
        // stage x (future phase keeps fed-back out in slot 51); prefetch next
        if (t < TSEQ && tid < BT)
            As[tid * ASTR + 51] = __float2half_rn(xcur);
        if (tid < BT && t + 1 < TSEQ)
            xnext = x[(size_t)(gb0 + tid) * TSEQ + (t + 1)];
        __syncthreads();                              // S1: x staged

#pragma unroll 1
        for (int L = 0; L < 2; L++) {
            const uint32_t* WL = Ws + L * NLAY_OFF;
            // ---- A fragments (reads h / x / bias rows of As) ----
            uint32_t a[4][4];
            {
                int r0 = mg * 16 + g;
#pragma unroll
                for (int kt = 0; kt < 4; kt++) {
                    int c0 = kt * 16 + 2 * tig;
                    a[kt][0] = *(const uint32_t*)&As[r0 * ASTR + c0];
                    a[kt][1] = *(const uint32_t*)&As[(r0 + 8) * ASTR + c0];
                    a[kt][2] = *(const uint32_t*)&As[r0 * ASTR + c0 + 8];
                    a[kt][3] = *(const uint32_t*)&As[(r0 + 8) * ASTR + c0 + 8];
                }
            }
            if (L == 0) __syncthreads();              // S2: all As reads done
                                                      // before act1 rewrites h

            // ---- 7 n-tiles: mma + in-register activation ----
#pragma unroll
            for (int ni = 0; ni < 7; ni++) {
                int nt = ntBeg + ni;
                uint32_t b0[4], b1[4];
#pragma unroll
                for (int kt = 0; kt < 4; kt++) {
                    uint2 bb = *(const uint2*)&WL[(((kt * 26) + nt) * 32 + lane) * 2];
                    b0[kt] = bb.x; b1[kt] = bb.y;
                }
                float d0 = 0.f, d1 = 0.f, d2 = 0.f, d3 = 0.f;
#pragma unroll
                for (int kt = 0; kt < 4; kt++) {
                    asm volatile(
                        "mma.sync.aligned.m16n8k16.row.col.f32.f16.f16.f32 "
                        "{%0,%1,%2,%3},{%4,%5,%6,%7},{%8,%9},{%0,%1,%2,%3};\n"
                        : "+f"(d0), "+f"(d1), "+f"(d2), "+f"(d3)
                        : "r"(a[kt][0]), "r"(a[kt][1]), "r"(a[kt][2]), "r"(a[kt][3]),
                          "r"(b0[kt]), "r"(b1[kt]));
                }
                // pair-exchange: even lane keeps rows g (i,f) + gets (g,o);
                // odd lane keeps rows g+8 (g,o) + gets (i,f)
                float s0 = oddl ? d0 : d2;
                float s1 = oddl ? d1 : d3;
                float x0 = __shfl_xor_sync(0xffffffffu, s0, 1);
                float x1 = __shfl_xor_sync(0xffffffffu, s1, 1);
                float gi = oddl ? x0 : d0;
                float gf = oddl ? x1 : d1;
                float gz = oddl ? d2 : x0;
                float go = oddl ? d3 : x1;
                int j = 2 * nt + (tig >> 1);
                if (j < 51) {
                    float i_ = sig_ap(gi);
                    float f_ = sig_ap(gf);
                    float z_ = tanh_ap(gz);
                    float o_ = sig_ap(go);
                    float c  = fmaf(f_, Cs[myrow * CSTR + j], i_ * z_);
                    if (L == 0) {
                        Cs[myrow * CSTR + j] = c;
                        As[myrow * ASTR + j] = __float2half_rn(o_ * tanh_ap(c));
                    } else {
                        Rs[myrow * RSTR + j] = o_ * tanh_ap(c) * woj[ni];
                    }
                }
            }
            __syncthreads();       // S3: h1 visible / S4: Rs visible
        }

        // ---- emit: out[b] = sum_j Rs[b][j] + bout; feed back into slot 51 ----
        {
            int row = tid >> 3, q = tid & 7;
            int jb = (q < 3) ? q * 7 : 21 + (q - 3) * 6;
            int jc = (q < 3) ? 7 : 6;
            const float* rr = Rs + row * RSTR + jb;
            float s = 0.0f;
#pragma unroll
            for (int k = 0; k < 7; k++)
                if (k < jc) s += rr[k];
            s += __shfl_xor_sync(0xffffffffu, s, 1);
            s += __shfl_xor_sync(0xffffffffu, s, 2);
            s += __shfl_xor_sync(0xffffffffu, s, 4);
            if (q == 0) {
                float o = s + bo;
                out[(size_t)(gb0 + row) * TTOT + t] = o;
                As[row * ASTR + 51] = __float2half_rn(o);
            }
        }
        xcur = xnext;
        __syncthreads();           // S5: end of step
    }
}

// ---------------------------------------------------------------------------
extern "C" void kernel_launch(void* const* d_in, const int* in_sizes, int n_in,
                              void* d_out, int out_size) {
    const float* x    = (const float*)d_in[0];
    const float* Wih1 = (const float*)d_in[1];
    const float* Whh1 = (const float*)d_in[2];
    const float* bih1 = (const float*)d_in[3];
    const float* bhh1 = (const float*)d_in[4];
    const float* Wih2 = (const float*)d_in[5];
    const float* Whh2 = (const float*)d_in[6];
    const float* bih2 = (const float*)d_in[7];
    const float* bhh2 = (const float*)d_in[8];
    const float* Wout = (const float*)d_in[9];
    const float* bouT = (const float*)d_in[10];
    float* out = (float*)d_out;

    cudaFuncSetAttribute(lstm_main, cudaFuncAttributeMaxDynamicSharedMemorySize, 70912);

    prep_weights<<<52, 256>>>(Wih1, Whh1, bih1, bhh1, Wih2, Whh2, bih2, bhh2);
    lstm_main<<<NCTA, TPB, 70912>>>(x, Wout, bouT, out);
}

// round 6
// speedup vs baseline: 2.5138x; 1.2831x over previous
#include <cuda_runtime.h>
#include <cuda_fp16.h>
#include <cstdint>

// LSTMPredictor: persistent-CTA fused 2-layer LSTM.
// All weights in REGISTERS (B-fragments, 64 regs/thread), c-state in registers,
// in-register activations via D-fragment pair exchange, double-buffered h/x
// operand matrix in SMEM (3 barriers/step).
//
// Grid 256 CTAs x 256 thr, BT=32 rows/CTA, 2 CTAs/SM.
// Gate GEMV: fp16 mma.m16n8k16, G[32 x 256pad] = A[32 x 64] @ W.
//   K: 0..50 h, 51 x/out, 52 bias(1.0), 53..63 zero
//   N: gate rows permuted n = 4j+q, q={i,f,g,o}; nt padded 26->32 (zeros).
// Warp w owns n-tiles 4w..4w+3 for BOTH m-tiles; lane site map is static so
// c lives in creg[mt][ni].

#define NLAY_OFF 8192
#define WF_TOTAL 16384
#define ASTR 72
#define RSTR 9
#define BT   32
#define TPB  256
#define TSEQ 2048
#define TTOT 2112
#define NCTA 256

__device__ __align__(16) uint32_t d_Wf[WF_TOTAL];

__device__ __forceinline__ float tanh_ap(float x) {
    float y; asm("tanh.approx.f32 %0, %1;" : "=f"(y) : "f"(x)); return y;
}
__device__ __forceinline__ float sig_ap(float x) {
    return fmaf(tanh_ap(0.5f * x), 0.5f, 0.5f);
}

// ---------------------------------------------------------------------------
// Fragment-ordered fp16 weights (R4/R5-verified encoding, nt padded to 32).
// u = L*8192 + ((kt*32 + nt)*32 + lane)*2 + r
// pair = W[k0][n], W[k0+1][n]; k0 = kt*16 + r*8 + 2*(lane&3); n = nt*8 + (lane>>2)
// n -> gate row: j = n>>2, q = n&3, row = q*51 + j
__global__ void prep_weights(const float* __restrict__ Wih1, const float* __restrict__ Whh1,
                             const float* __restrict__ bih1, const float* __restrict__ bhh1,
                             const float* __restrict__ Wih2, const float* __restrict__ Whh2,
                             const float* __restrict__ bih2, const float* __restrict__ bhh2) {
    int u = blockIdx.x * blockDim.x + threadIdx.x;
    if (u >= WF_TOTAL) return;
    int L    = u / NLAY_OFF;
    int w    = u - L * NLAY_OFF;
    int r    = w & 1;
    int lane = (w >> 1) & 31;
    int t2   = w >> 6;
    int nt   = t2 & 31;
    int kt   = t2 >> 5;
    int n    = nt * 8 + (lane >> 2);
    int k0   = kt * 16 + r * 8 + 2 * (lane & 3);
    float v[2];
#pragma unroll
    for (int i = 0; i < 2; i++) {
        int k = k0 + i;
        float val = 0.0f;
        if (n < 204) {
            int j = n >> 2, q = n & 3;
            int row = q * 51 + j;
            if (k < 51)
                val = (L == 0) ? Whh1[row * 51 + k]
                               : (Wih2[row * 51 + k] + Whh2[row * 51 + k]);
            else if (k == 51)
                val = (L == 0) ? Wih1[row] : 0.0f;
            else if (k == 52)
                val = (L == 0) ? (bih1[row] + bhh1[row]) : (bih2[row] + bhh2[row]);
        }
        v[i] = val;
    }
    __half2 h = __floats2half2_rn(v[0], v[1]);
    d_Wf[u] = *(uint32_t*)&h;
}

// ---------------------------------------------------------------------------
__global__ void __launch_bounds__(TPB, 2)
lstm_main(const float* __restrict__ x,
          const float* __restrict__ Wout, const float* __restrict__ bout,
          float* __restrict__ out) {
    __shared__ __half Asb[2][BT * ASTR];     // double-buffered A (h | x | 1)
    __shared__ float  Rs2[BT * RSTR];        // per-(row,warp) layer-2 partials

    const int tid  = threadIdx.x;
    const int lane = tid & 31;
    const int wrp  = tid >> 5;
    const int gb0  = blockIdx.x * BT;
    const int g    = lane >> 2, tig = lane & 3;
    const int oddl = tig & 1;
    const int ntBeg = wrp * 4;

    // ---- one-time init ----
    for (int i = tid; i < BT * ASTR; i += TPB) {
        __half v = __float2half_rn((i % ASTR) == 52 ? 1.0f : 0.0f);
        Asb[0][i] = v; Asb[1][i] = v;
    }
    if (tid < BT)
        Asb[0][tid * ASTR + 51] = __float2half_rn(x[(size_t)(gb0 + tid) * TSEQ]);
    float xnext = (tid < BT) ? x[(size_t)(gb0 + tid) * TSEQ + 1] : 0.0f;

    // B fragments -> registers (64 regs)
    uint32_t Br[2][4][4][2];                 // [L][ni][kt][r]
#pragma unroll
    for (int L = 0; L < 2; L++)
#pragma unroll
        for (int ni = 0; ni < 4; ni++)
#pragma unroll
            for (int kt = 0; kt < 4; kt++) {
                uint2 v = *(const uint2*)&d_Wf[L * NLAY_OFF +
                            (((kt * 32) + (ntBeg + ni)) * 32 + lane) * 2];
                Br[L][ni][kt][0] = v.x; Br[L][ni][kt][1] = v.y;
            }

    const float bo = bout[0];
    float woj[4];
#pragma unroll
    for (int ni = 0; ni < 4; ni++) {
        int j = 2 * (ntBeg + ni) + (tig >> 1);
        woj[ni] = (j < 51) ? Wout[j] : 0.0f;
    }

    float creg[2][4];
#pragma unroll
    for (int mt = 0; mt < 2; mt++)
#pragma unroll
        for (int ni = 0; ni < 4; ni++) creg[mt][ni] = 0.0f;

    __syncthreads();

#pragma unroll 1
    for (int t = 0; t < TTOT; t++) {
        const __half* Ac = Asb[t & 1];
        __half*       An = Asb[(t & 1) ^ 1];

        // ================= Layer 1 (recurrent) =================
#pragma unroll
        for (int mt = 0; mt < 2; mt++) {
            uint32_t a[4][4];
            const int r0 = mt * 16 + g;
#pragma unroll
            for (int kt = 0; kt < 4; kt++) {
                int c0 = kt * 16 + 2 * tig;
                a[kt][0] = *(const uint32_t*)&Ac[r0 * ASTR + c0];
                a[kt][1] = *(const uint32_t*)&Ac[(r0 + 8) * ASTR + c0];
                a[kt][2] = *(const uint32_t*)&Ac[r0 * ASTR + c0 + 8];
                a[kt][3] = *(const uint32_t*)&Ac[(r0 + 8) * ASTR + c0 + 8];
            }
            const int myrow = r0 + (oddl ? 8 : 0);
#pragma unroll
            for (int ni = 0; ni < 4; ni++) {
                float d0 = 0.f, d1 = 0.f, d2 = 0.f, d3 = 0.f;
#pragma unroll
                for (int kt = 0; kt < 4; kt++) {
                    asm volatile(
                        "mma.sync.aligned.m16n8k16.row.col.f32.f16.f16.f32 "
                        "{%0,%1,%2,%3},{%4,%5,%6,%7},{%8,%9},{%0,%1,%2,%3};\n"
                        : "+f"(d0), "+f"(d1), "+f"(d2), "+f"(d3)
                        : "r"(a[kt][0]), "r"(a[kt][1]), "r"(a[kt][2]), "r"(a[kt][3]),
                          "r"(Br[0][ni][kt][0]), "r"(Br[0][ni][kt][1]));
                }
                float s0 = oddl ? d0 : d2;
                float s1 = oddl ? d1 : d3;
                float x0 = __shfl_xor_sync(0xffffffffu, s0, 1);
                float x1 = __shfl_xor_sync(0xffffffffu, s1, 1);
                float gi = oddl ? x0 : d0;
                float gf = oddl ? x1 : d1;
                float gz = oddl ? d2 : x0;
                float go = oddl ? d3 : x1;
                float i_ = sig_ap(gi);
                float f_ = sig_ap(gf);
                float z_ = tanh_ap(gz);
                float o_ = sig_ap(go);
                float c  = fmaf(f_, creg[mt][ni], i_ * z_);
                creg[mt][ni] = c;
                int j = 2 * (ntBeg + ni) + (tig >> 1);
                if (j < 51)
                    An[myrow * ASTR + j] = __float2half_rn(o_ * tanh_ap(c));
            }
        }
        __syncthreads();                      // S3: h1 visible

        // ================= Layer 2 (stateless) + row partials =================
        float racc[2] = {0.0f, 0.0f};
#pragma unroll
        for (int mt = 0; mt < 2; mt++) {
            uint32_t a[4][4];
            const int r0 = mt * 16 + g;
#pragma unroll
            for (int kt = 0; kt < 4; kt++) {
                int c0 = kt * 16 + 2 * tig;
                a[kt][0] = *(const uint32_t*)&An[r0 * ASTR + c0];
                a[kt][1] = *(const uint32_t*)&An[(r0 + 8) * ASTR + c0];
                a[kt][2] = *(const uint32_t*)&An[r0 * ASTR + c0 + 8];
                a[kt][3] = *(const uint32_t*)&An[(r0 + 8) * ASTR + c0 + 8];
            }
#pragma unroll
            for (int ni = 0; ni < 4; ni++) {
                float d0 = 0.f, d1 = 0.f, d2 = 0.f, d3 = 0.f;
#pragma unroll
                for (int kt = 0; kt < 4; kt++) {
                    asm volatile(
                        "mma.sync.aligned.m16n8k16.row.col.f32.f16.f16.f32 "
                        "{%0,%1,%2,%3},{%4,%5,%6,%7},{%8,%9},{%0,%1,%2,%3};\n"
                        : "+f"(d0), "+f"(d1), "+f"(d2), "+f"(d3)
                        : "r"(a[kt][0]), "r"(a[kt][1]), "r"(a[kt][2]), "r"(a[kt][3]),
                          "r"(Br[1][ni][kt][0]), "r"(Br[1][ni][kt][1]));
                }
                float s0 = oddl ? d0 : d2;
                float s1 = oddl ? d1 : d3;
                float x0 = __shfl_xor_sync(0xffffffffu, s0, 1);
                float x1 = __shfl_xor_sync(0xffffffffu, s1, 1);
                float gi = oddl ? x0 : d0;
                float gf = oddl ? x1 : d1;
                float gz = oddl ? d2 : x0;
                float go = oddl ? d3 : x1;
                float i_ = sig_ap(gi);
                float f_ = sig_ap(gf);
                float z_ = tanh_ap(gz);
                float o_ = sig_ap(go);
                float c2 = fmaf(f_, creg[mt][ni], i_ * z_);   // c NOT updated
                racc[mt] += o_ * tanh_ap(c2) * woj[ni];
            }
        }
        // fold the two j's (tig, tig^2 share a row) -> one partial per (row,warp)
        racc[0] += __shfl_xor_sync(0xffffffffu, racc[0], 2);
        racc[1] += __shfl_xor_sync(0xffffffffu, racc[1], 2);
        if ((tig >> 1) == 0) {
            int rowA = g + (oddl ? 8 : 0);
            Rs2[rowA * RSTR + wrp]        = racc[0];
            Rs2[(rowA + 16) * RSTR + wrp] = racc[1];
        }
        __syncthreads();                      // S4: partials visible, An reads done

        // ================= emit + feedback / x-stage =================
        {
            int row = tid >> 3, q = tid & 7;
            float s = Rs2[row * RSTR + q];
            s += __shfl_xor_sync(0xffffffffu, s, 1);
            s += __shfl_xor_sync(0xffffffffu, s, 2);
            s += __shfl_xor_sync(0xffffffffu, s, 4);
            if (q == 0) {
                float o = s + bo;
                out[(size_t)(gb0 + row) * TTOT + t] = o;
                if (t + 1 >= TSEQ)
                    An[row * ASTR + 51] = __float2half_rn(o);
            }
        }
        if (tid < BT) {
            if (t + 1 < TSEQ)
                An[tid * ASTR + 51] = __float2half_rn(xnext);
            if (t + 2 < TSEQ)
                xnext = x[(size_t)(gb0 + tid) * TSEQ + (t + 2)];
        }
        __syncthreads();                      // S5: step complete
    }
}

// ---------------------------------------------------------------------------
extern "C" void kernel_launch(void* const* d_in, const int* in_sizes, int n_in,
                              void* d_out, int out_size) {
    const float* x    = (const float*)d_in[0];
    const float* Wih1 = (const float*)d_in[1];
    const float* Whh1 = (const float*)d_in[2];
    const float* bih1 = (const float*)d_in[3];
    const float* bhh1 = (const float*)d_in[4];
    const float* Wih2 = (const float*)d_in[5];
    const float* Whh2 = (const float*)d_in[6];
    const float* bih2 = (const float*)d_in[7];
    const float* bhh2 = (const float*)d_in[8];
    const float* Wout = (const float*)d_in[9];
    const float* bouT = (const float*)d_in[10];
    float* out = (float*)d_out;

    prep_weights<<<64, 256>>>(Wih1, Whh1, bih1, bhh1, Wih2, Whh2, bih2, bhh2);
    lstm_main<<<NCTA, TPB>>>(x, Wout, bouT, out);
}